// round 13
// baseline (speedup 1.0000x reference)
#include <cuda_runtime.h>
#include <cstdint>
#include <math.h>

#define T_LEN  2048
#define D_EMB  300
#define H_DIM  256
#define G4     1024
#define K_TAGS 48
#define START_TAG 46
#define STOP_TAG  47

// ---------------- scratch (device globals; no allocation) ----------------
__device__ float g_xg[2][T_LEN * G4];       // input projections per dir [T, 4H]
__device__ float g_hs[2][T_LEN * H_DIM];    // hidden states per dir, time-aligned
__device__ float g_feats[T_LEN * K_TAGS];   // emission features [T, K]
__device__ int   g_ready[2][32];            // xg tile ready count (16 = full)
__device__ int   g_feats_ready[32];         // feats 64-step tile ready flags

// ---------------- f32x2 helpers ----------------
__device__ __forceinline__ unsigned long long pack2(float lo, float hi) {
    unsigned long long r;
    asm("mov.b64 %0, {%1,%2};" : "=l"(r) : "f"(lo), "f"(hi));
    return r;
}
__device__ __forceinline__ void unpack2(unsigned long long v, float& lo, float& hi) {
    asm("mov.b64 {%0,%1}, %2;" : "=f"(lo), "=f"(hi) : "l"(v));
}
__device__ __forceinline__ unsigned long long mul2(unsigned long long a, unsigned long long b) {
    unsigned long long d;
    asm("mul.rn.f32x2 %0, %1, %2;" : "=l"(d) : "l"(a), "l"(b));
    return d;
}
__device__ __forceinline__ unsigned long long fma2(unsigned long long a, unsigned long long b,
                                                   unsigned long long c) {
    unsigned long long d;
    asm("fma.rn.f32x2 %0, %1, %2, %3;" : "=l"(d) : "l"(a), "l"(b), "l"(c));
    return d;
}
__device__ __forceinline__ int ld_acquire_gpu(const int* p) {
    int v;
    asm volatile("ld.acquire.gpu.s32 %0, [%1];" : "=r"(v) : "l"(p) : "memory");
    return v;
}

// ================= MEGA KERNEL 1: xg-GEMM workers + LSTM clusters =================
// grid (8, 18), cluster (8,1,1), 512 threads.
//  y < 2  : LSTM 8-CTA cluster for direction y (frozen champion protocol).
//  y >= 2 : 128 worker CTAs computing xg = gather(E,sent) @ W_ih^T + b_ih + b_hh
//           for BOTH dirs, t-tile-major so early timesteps complete first.
__global__ void __launch_bounds__(512, 1) __cluster_dims__(8, 1, 1)
mega_kernel(const int* __restrict__ sent, const float* __restrict__ E,
            const float* __restrict__ Wihf, const float* __restrict__ Whhf,
            const float* __restrict__ bihf, const float* __restrict__ bhhf,
            const float* __restrict__ Wihb, const float* __restrict__ Whhb,
            const float* __restrict__ bihb, const float* __restrict__ bhhb) {
    __shared__ float h_buf[2][H_DIM];
    __shared__ float As[12][64];
    __shared__ float Bs[12][64];

    int tid = threadIdx.x;

    if (blockIdx.y >= 2) {
        // ---------------- xg-GEMM worker role ----------------
        int worker = (int)(blockIdx.y - 2) * 8 + (int)blockIdx.x;   // 0..127
#pragma unroll 1
        for (int pass = 0; pass < 8; pass++) {
            int tile = worker + pass * 128;      // 0..1023, t-tile-major
            int ttile = tile >> 5;
            int rem = tile & 31;
            int rtile = rem >> 1;
            int dir = rem & 1;
            int t0 = ttile * 64;
            int r0 = rtile * 64;
            const float* Wih = dir ? Wihb : Wihf;
            const float* b1 = dir ? bihb : bihf;
            const float* b2 = dir ? bhhb : bhhf;

            int tx = tid & 15;       // 4 output cols
            int ty = tid >> 4;       // 32 groups of 2 output rows (time)
            float acc[2][4];
#pragma unroll
            for (int i = 0; i < 2; i++)
#pragma unroll
                for (int j = 0; j < 4; j++) acc[i][j] = 0.f;

            for (int k0 = 0; k0 < D_EMB; k0 += 12) {
#pragma unroll
                for (int l2 = 0; l2 < 2; l2++) {
                    int idx = tid + l2 * 512;
                    if (idx < 768) {
                        int row = idx / 12;
                        int kk = idx - row * 12;
                        int tg = t0 + row;
                        int ts = dir ? (T_LEN - 1 - tg) : tg;
                        long long vrow = sent[ts];
                        As[kk][row] = E[vrow * D_EMB + k0 + kk];
                        Bs[kk][row] = Wih[(size_t)(r0 + row) * D_EMB + k0 + kk];
                    }
                }
                __syncthreads();
#pragma unroll
                for (int kk = 0; kk < 12; kk++) {
                    float ra0 = As[kk][ty * 2];
                    float ra1 = As[kk][ty * 2 + 1];
                    float rb[4];
#pragma unroll
                    for (int j = 0; j < 4; j++) rb[j] = Bs[kk][tx * 4 + j];
#pragma unroll
                    for (int j = 0; j < 4; j++) {
                        acc[0][j] += ra0 * rb[j];
                        acc[1][j] += ra1 * rb[j];
                    }
                }
                __syncthreads();
            }

#pragma unroll
            for (int i = 0; i < 2; i++) {
                int t = t0 + ty * 2 + i;
#pragma unroll
                for (int j = 0; j < 4; j++) {
                    int r = r0 + tx * 4 + j;
                    g_xg[dir][(size_t)t * G4 + r] = acc[i][j] + b1[r] + b2[r];
                }
            }
            __syncthreads();
            __threadfence();
            if (tid == 0) atomicAdd(&g_ready[dir][ttile], 1);
        }
        return;
    }

    // ---------------- LSTM cluster role (frozen champion) ----------------
    int dir = blockIdx.y;
    const float* Whh = dir ? Whhb : Whhf;
    const float* xg = g_xg[dir];
    float* hs = g_hs[dir];

    uint32_t rank;
    asm("mov.u32 %0, %%cluster_ctarank;" : "=r"(rank));

    int w = tid >> 5;
    int l = tid & 31;
    int r = (l >> 2) & 7;          // W row this lane finalizes (lane bits 4,3,2)
    int gate = r & 3;
    int du = r >> 2;               // which of the warp's 2 units (== l>>4)
    int xg_col = gate * H_DIM + (int)rank * 32 + 2 * w + du;

    unsigned long long w2[8][4];
#pragma unroll
    for (int q = 0; q < 8; q++) {
        int row = (q & 3) * H_DIM + (int)rank * 32 + 2 * w + (q >> 2);
        const float4* p = (const float4*)(Whh + (size_t)row * H_DIM + l * 8);
        float4 a = p[0];
        float4 b = p[1];
        w2[q][0] = pack2(a.x, a.y); w2[q][1] = pack2(a.z, a.w);
        w2[q][2] = pack2(b.x, b.y); w2[q][3] = pack2(b.z, b.w);
    }

    if (tid < 2 * H_DIM) ((float*)h_buf)[tid] = 0.f;
    uint32_t hb = (uint32_t)__cvta_generic_to_shared(&h_buf[0][0]);

    uint32_t rH[8];
#pragma unroll
    for (int tg = 0; tg < 8; tg++) {
        asm("mapa.shared::cluster.u32 %0, %1, %2;" : "=r"(rH[tg]) : "r"(hb), "r"(tg));
    }

    __syncthreads();
    asm volatile("barrier.cluster.arrive.aligned;" ::: "memory");
    asm volatile("barrier.cluster.wait.aligned;" ::: "memory");

    // wait for xg tile 0 of this direction
    if (tid == 0) {
        while (ld_acquire_gpu(&g_ready[dir][0]) < 16) {}
    }
    __syncthreads();

    float c_reg = 0.f;
    float xg_pref = xg[xg_col];    // xg for t=0
    const float LOG2E = 1.4426950408889634f;
    const float act_a = (gate == 2) ? (2.f * LOG2E) : (-LOG2E);
    const bool  is_tanh = (gate == 2);

#pragma unroll 1
    for (int t = 0; t < T_LEN; t++) {
        int cur = t & 1;
        int nxt = cur ^ 1;

        // prefetch of xg[t+1] during this step crosses into tile (t+1)>>6
        if ((t & 63) == 63 && t + 1 < T_LEN) {
            if (tid == 0) {
                int need = (t + 1) >> 6;
                while (ld_acquire_gpu(&g_ready[dir][need]) < 16) {}
            }
            __syncthreads();
        }

        float4 ha = *(const float4*)&h_buf[cur][l * 8];
        float4 hc = *(const float4*)&h_buf[cur][l * 8 + 4];
        unsigned long long h2[4] = { pack2(ha.x, ha.y), pack2(ha.z, ha.w),
                                     pack2(hc.x, hc.y), pack2(hc.z, hc.w) };
        float v[8];
#pragma unroll
        for (int q = 0; q < 8; q++) {
            unsigned long long acc = mul2(w2[q][0], h2[0]);
            acc = fma2(w2[q][1], h2[1], acc);
            acc = fma2(w2[q][2], h2[2], acc);
            acc = fma2(w2[q][3], h2[3], acc);
            float lo, hi;
            unpack2(acc, lo, hi);
            v[q] = lo + hi;
        }

        // reduce-scatter onto lane bits 4,3,2 (row = (l>>2)&7)
#pragma unroll
        for (int i = 0; i < 4; i++) {
            float send = (l & 16) ? v[i] : v[i + 4];
            float recv = __shfl_xor_sync(0xffffffffu, send, 16);
            float keep = (l & 16) ? v[i + 4] : v[i];
            v[i] = keep + recv;
        }
#pragma unroll
        for (int i = 0; i < 2; i++) {
            float send = (l & 8) ? v[i] : v[i + 2];
            float recv = __shfl_xor_sync(0xffffffffu, send, 8);
            float keep = (l & 8) ? v[i + 2] : v[i];
            v[i] = keep + recv;
        }
        {
            float send = (l & 4) ? v[0] : v[1];
            float recv = __shfl_xor_sync(0xffffffffu, send, 4);
            float keep = (l & 4) ? v[1] : v[0];
            v[0] = keep + recv;
        }
        // combine the 4 partials living at lane bits 1,0
        float x = v[0];
        x += __shfl_xor_sync(0xffffffffu, x, 1);
        x += __shfl_xor_sync(0xffffffffu, x, 2);

        float pre = x + xg_pref;

        // branch-free activation: gate 2 -> tanh, else sigmoid (EX2 + RCP)
        float e = exp2f(act_a * pre);
        float z = __fdividef(1.f, 1.f + e);
        float act = is_tanh ? fmaf(-2.f, z, 1.f) : z;

        // gather i,f,g,o for this lane's unit du: rows du*4+g at lanes 16du+4g
        int gbase = du << 4;
        float iv = __shfl_sync(0xffffffffu, act, gbase);
        float fv = __shfl_sync(0xffffffffu, act, gbase + 4);
        float gg = __shfl_sync(0xffffffffu, act, gbase + 8);
        float ov = __shfl_sync(0xffffffffu, act, gbase + 12);

        c_reg = fmaf(fv, c_reg, iv * gg);
        float e2 = exp2f(2.f * LOG2E * c_reg);
        float hval = ov * fmaf(-2.f, __fdividef(1.f, 1.f + e2), 1.f);
        // hval identical within each du half (lanes 0-15: unit 2w; 16-31: 2w+1)

        // single xor-16: every lane obtains the other unit's h
        float h_other = __shfl_xor_sync(0xffffffffu, hval, 16);

        uint32_t off = (uint32_t)((nxt * H_DIM + (int)rank * 32 + 2 * w) * 4);
        if (l < 8) {   // lanes 0-7: du=0 -> hval=h0, h_other=h1
            unsigned long long pk = pack2(hval, h_other);
            asm volatile("st.shared::cluster.b64 [%0], %1;"
                         :: "r"(rH[l] + off), "l"(pk) : "memory");
        }

        asm volatile("barrier.cluster.arrive.aligned;" ::: "memory");

        // issue next-step xg load inside the barrier window (latency hidden)
        if (t + 1 < T_LEN)
            xg_pref = xg[(size_t)(t + 1) * G4 + xg_col];

        if (l == 8) {  // du=0: hval=h0, h_other=h1
            int tout = dir ? (T_LEN - 1 - t) : t;
            *(float2*)&hs[(size_t)tout * H_DIM + rank * 32 + 2 * w] =
                make_float2(hval, h_other);
        }

        asm volatile("barrier.cluster.wait.aligned;" ::: "memory");
    }

    asm volatile("barrier.cluster.arrive.aligned;" ::: "memory");
    asm volatile("barrier.cluster.wait.aligned;" ::: "memory");

    // reset this dir's ready counters for the next graph replay
    if (rank == 0 && tid < 32) g_ready[dir][tid] = 0;
}

// ================= MEGA KERNEL 2: feats GEMM workers + Viterbi =================
// grid 33 CTAs x 256 threads. CTAs 0..31: one 64-timestep feats tile each,
// publish g_feats_ready[tile]=1 (threadfence + atomicExch). CTA 32: Viterbi
// (threads 0..95 active), polls a tile flag only at tile crossings (the featp
// prefetch is the sole feats read). Viterbi resets all flags at its end --
// safe because it observed every flag==1 (acquire) before resetting, so no
// feats CTA write can land after the reset; graph replay is deterministic.
#define FT_TT 64
#define VIT_SMEM (T_LEN * K_TAGS + 2 * K_TAGS * 4 + 16)
extern __shared__ unsigned char dyn_smem[];
__global__ void __launch_bounds__(256, 1)
feats_viterbi_kernel(const float* __restrict__ W_out,
                     const float* __restrict__ b_out,
                     const float* __restrict__ trans,
                     float* __restrict__ out) {
    int tid = threadIdx.x;

    if (blockIdx.x < 32) {
        // ---------------- feats tile role ----------------
        float (*As)[FT_TT]  = (float (*)[FT_TT])dyn_smem;               // [32][64]
        float (*Bs)[K_TAGS] = (float (*)[K_TAGS])(dyn_smem + 32 * FT_TT * 4);

        int t0 = (int)blockIdx.x * FT_TT;
        int tx = tid & 15;                // k-group: 3 tags
        int ty = tid >> 4;                // t-group: 4 steps

        float acc[4][3];
#pragma unroll
        for (int i = 0; i < 4; i++)
#pragma unroll
            for (int k = 0; k < 3; k++) acc[i][k] = 0.f;

        for (int j0 = 0; j0 < 2 * H_DIM; j0 += 32) {
#pragma unroll
            for (int i = 0; i < 8; i++) {
                int idx = tid + i * 256;        // 0..2047
                int jj = idx & 31;
                int tt = idx >> 5;
                int j = j0 + jj;
                float hv = (j < H_DIM)
                    ? g_hs[0][(size_t)(t0 + tt) * H_DIM + j]
                    : g_hs[1][(size_t)(t0 + tt) * H_DIM + (j - H_DIM)];
                As[jj][tt] = hv;
            }
#pragma unroll
            for (int i = 0; i < 6; i++) {
                int idx = tid + i * 256;        // 0..1535 = 32 j x 48 k
                int jj = idx & 31;
                int k = idx >> 5;               // 0..47
                Bs[jj][k] = W_out[(size_t)k * (2 * H_DIM) + j0 + jj];
            }
            __syncthreads();
#pragma unroll
            for (int jj = 0; jj < 32; jj++) {
                float a[4], b[3];
#pragma unroll
                for (int i = 0; i < 4; i++) a[i] = As[jj][ty * 4 + i];
#pragma unroll
                for (int k = 0; k < 3; k++) b[k] = Bs[jj][tx * 3 + k];
#pragma unroll
                for (int i = 0; i < 4; i++)
#pragma unroll
                    for (int k = 0; k < 3; k++) acc[i][k] += a[i] * b[k];
            }
            __syncthreads();
        }

#pragma unroll
        for (int i = 0; i < 4; i++) {
            int t = t0 + ty * 4 + i;
#pragma unroll
            for (int k = 0; k < 3; k++) {
                int kk = tx * 3 + k;
                g_feats[t * K_TAGS + kk] = acc[i][k] + b_out[kk];
            }
        }
        __syncthreads();
        __threadfence();
        if (tid == 0) atomicExch(&g_feats_ready[blockIdx.x], 1);
        return;
    }

    // ---------------- Viterbi role (threads 0..95) ----------------
    unsigned char* bptr = dyn_smem;                          // [T][48] u8 = 96KB
    float* fvs = (float*)(dyn_smem + T_LEN * K_TAGS);        // [2][48], 16B aligned
    int l = tid & 31;
    int wid = tid >> 5;                    // warp
    int tag = wid * 16 + (l & 15);
    int half = l >> 4;                     // 0 or 1
    int jlo = half * 24;
    bool active = (tid < 96);

    float tr[24];
    float featp = 0.f;
    if (active) {
#pragma unroll
        for (int j = 0; j < 24; j++) tr[j] = trans[tag * K_TAGS + jlo + j];
        if (half == 0) {
            fvs[tag] = (tag == START_TAG) ? 0.f : -10000.f;
            // wait for feats tile 0, then load featp(t=0)
            while (ld_acquire_gpu(&g_feats_ready[0]) == 0) {}
            featp = g_feats[tag];
        }
    }
    __syncthreads();

    for (int t = 0; t < T_LEN; t++) {
        int cur = (t & 1) * K_TAGS;
        int nxt = K_TAGS - cur;

        if (active) {
            // vectorized fv load: 24 floats = 6 x float4 (all 16B aligned)
            float vals[24];
            {
                const float4* fp = (const float4*)&fvs[cur + jlo];
#pragma unroll
                for (int q = 0; q < 6; q++)
                    *(float4*)&vals[q * 4] = fp[q];
            }

            float b0 = -3.4e38f, b1 = -3.4e38f, b2 = -3.4e38f, b3 = -3.4e38f;
            int a0 = 0, a1 = 1, a2 = 2, a3 = 3;
#pragma unroll
            for (int j = 0; j < 24; j += 4) {
                float s0 = vals[j]     + tr[j];
                float s1 = vals[j + 1] + tr[j + 1];
                float s2 = vals[j + 2] + tr[j + 2];
                float s3 = vals[j + 3] + tr[j + 3];
                if (s0 > b0) { b0 = s0; a0 = j; }
                if (s1 > b1) { b1 = s1; a1 = j + 1; }
                if (s2 > b2) { b2 = s2; a2 = j + 2; }
                if (s3 > b3) { b3 = s3; a3 = j + 3; }
            }
            float bv = b0; int ba = a0;
            if (b1 > bv || (b1 == bv && a1 < ba)) { bv = b1; ba = a1; }
            if (b2 > bv || (b2 == bv && a2 < ba)) { bv = b2; ba = a2; }
            if (b3 > bv || (b3 == bv && a3 < ba)) { bv = b3; ba = a3; }
            ba += jlo;

            // cross-half combine inside the warp (half0 <-> half1 at xor 16)
            float ov = __shfl_xor_sync(0xffffffffu, bv, 16);
            int   oa = __shfl_xor_sync(0xffffffffu, ba, 16);
            if (half == 0) {
                // strict > : ties keep half0 (smaller prev indices) = jnp.argmax
                if (ov > bv) { bv = ov; ba = oa; }
                fvs[nxt + tag] = bv + featp;
                bptr[t * K_TAGS + tag] = (unsigned char)ba;
                if (t + 1 < T_LEN) {
                    // crossing into a new feats tile: poll its flag first
                    if ((t & 63) == 63) {
                        int need = (t + 1) >> 6;
                        while (ld_acquire_gpu(&g_feats_ready[need]) == 0) {}
                    }
                    featp = g_feats[(t + 1) * K_TAGS + tag];
                }
            }
        }
        __syncthreads();
    }

    if (tid == 0) {
        int cur = (T_LEN & 1) * K_TAGS;   // = 0 for even T
        float best = -3.4e38f;
        int btag = 0;
#pragma unroll
        for (int j = 0; j < K_TAGS; j++) {
            float s = fvs[cur + j] + trans[STOP_TAG * K_TAGS + j];
            if (s > best) { best = s; btag = j; }
        }
        out[0] = best;
        for (int t = T_LEN - 1; t >= 0; t--) {
            out[1 + t] = (float)btag;
            btag = bptr[t * K_TAGS + btag];
        }
    }
    __syncthreads();
    // reset feats flags for next graph replay (all were observed == 1)
    if (tid < 32) g_feats_ready[tid] = 0;
}

// ---------------- launch ----------------
extern "C" void kernel_launch(void* const* d_in, const int* in_sizes, int n_in,
                              void* d_out, int out_size) {
    const int*   sent   = (const int*)d_in[0];
    const float* E      = (const float*)d_in[1];
    const float* W_ih_f = (const float*)d_in[2];
    const float* W_hh_f = (const float*)d_in[3];
    const float* b_ih_f = (const float*)d_in[4];
    const float* b_hh_f = (const float*)d_in[5];
    const float* W_ih_b = (const float*)d_in[6];
    const float* W_hh_b = (const float*)d_in[7];
    const float* b_ih_b = (const float*)d_in[8];
    const float* b_hh_b = (const float*)d_in[9];
    const float* W_out  = (const float*)d_in[10];
    const float* b_out  = (const float*)d_in[11];
    const float* trans  = (const float*)d_in[12];
    float* out = (float*)d_out;

    cudaFuncSetAttribute(feats_viterbi_kernel,
                         cudaFuncAttributeMaxDynamicSharedMemorySize, VIT_SMEM);

    // gather + xg GEMM + both LSTM directions in ONE launch
    mega_kernel<<<dim3(8, 18, 1), 512>>>(sent, E,
                                         W_ih_f, W_hh_f, b_ih_f, b_hh_f,
                                         W_ih_b, W_hh_b, b_ih_b, b_hh_b);

    // feats GEMM (CTAs 0-31) + Viterbi (CTA 32) in ONE launch, flag-synced
    feats_viterbi_kernel<<<33, 256, VIT_SMEM>>>(W_out, b_out, trans, out);
}